// round 2
// baseline (speedup 1.0000x reference)
#include <cuda_runtime.h>
#include <math.h>

#define VF_D  4096
#define HID_D 2048
#define EMB_D 512
#define BB    256
#define NNEG  512

// Scratch (no allocations allowed anywhere)
__device__ float g_hidden[BB * HID_D];   // [256, 2048]
__device__ float g_emb[BB * EMB_D];      // [256, 512]

// ---------------------------------------------------------------------------
// init: g_emb[b, e] = b_embed[e]  (split-K GEMM2 accumulates on top)
// ---------------------------------------------------------------------------
__global__ void init_emb_kernel(const float* __restrict__ bias) {
    int i = blockIdx.x * blockDim.x + threadIdx.x;
    if (i < BB * EMB_D) g_emb[i] = bias[i & (EMB_D - 1)];
}

// ---------------------------------------------------------------------------
// C[M,N] = A[M,lda] @ B[N,lda]^T (+ bias)   (NT gemm, K contiguous in both)
// Tiles: BM=32, BN=64, BK=16, 128 threads, 4x4 micro-tile per thread.
// gridDim.z > 1 => split-K: atomicAdd into pre-initialized C (bias ignored).
// Fixed shapes divide all tiles exactly.
// ---------------------------------------------------------------------------
__global__ __launch_bounds__(128) void sgemm_nt(
    const float* __restrict__ A, const float* __restrict__ Bw,
    const float* __restrict__ bias, float* __restrict__ C,
    int lda, int N, int kchunk)
{
    __shared__ float As[16][36];   // [k][m]; 36*4=144B rows (16B aligned), padded
    __shared__ float Bs[16][68];   // [k][n]; 68*4=272B rows (16B aligned), padded

    const int tid = threadIdx.x;
    const int m0 = blockIdx.y * 32;
    const int n0 = blockIdx.x * 64;
    const int kbase = blockIdx.z * kchunk;

    // global-load assignments (all float4 along K)
    const int a_row = tid >> 2;            // 0..31
    const int a_k   = (tid & 3) * 4;       // 0,4,8,12
    const int b_row = tid >> 1;            // 0..63
    const int b_k   = (tid & 1) * 8;       // 0,8

    const float* Aptr = A  + (size_t)(m0 + a_row) * lda + kbase + a_k;
    const float* Bptr = Bw + (size_t)(n0 + b_row) * lda + kbase + b_k;

    // compute assignments: 8x16 thread grid, 4x4 micro-tile
    const int tm = (tid >> 4) * 4;         // 0..28
    const int tn = (tid & 15) * 4;         // 0..60

    float acc[4][4] = {};

    // prefetch first k-tile into registers
    float4 av  = *(const float4*)(Aptr);
    float4 bv0 = *(const float4*)(Bptr);
    float4 bv1 = *(const float4*)(Bptr + 4);

    for (int k0 = 0; k0 < kchunk; k0 += 16) {
        As[a_k    ][a_row] = av.x;
        As[a_k + 1][a_row] = av.y;
        As[a_k + 2][a_row] = av.z;
        As[a_k + 3][a_row] = av.w;
        Bs[b_k    ][b_row] = bv0.x;
        Bs[b_k + 1][b_row] = bv0.y;
        Bs[b_k + 2][b_row] = bv0.z;
        Bs[b_k + 3][b_row] = bv0.w;
        Bs[b_k + 4][b_row] = bv1.x;
        Bs[b_k + 5][b_row] = bv1.y;
        Bs[b_k + 6][b_row] = bv1.z;
        Bs[b_k + 7][b_row] = bv1.w;
        __syncthreads();

        // issue next k-tile's global loads early (hidden behind 256 FFMAs)
        if (k0 + 16 < kchunk) {
            av  = *(const float4*)(Aptr + k0 + 16);
            bv0 = *(const float4*)(Bptr + k0 + 16);
            bv1 = *(const float4*)(Bptr + k0 + 20);
        }

        #pragma unroll
        for (int k = 0; k < 16; k++) {
            float4 a4 = *(const float4*)&As[k][tm];
            float4 b4 = *(const float4*)&Bs[k][tn];
            acc[0][0] = fmaf(a4.x, b4.x, acc[0][0]);
            acc[0][1] = fmaf(a4.x, b4.y, acc[0][1]);
            acc[0][2] = fmaf(a4.x, b4.z, acc[0][2]);
            acc[0][3] = fmaf(a4.x, b4.w, acc[0][3]);
            acc[1][0] = fmaf(a4.y, b4.x, acc[1][0]);
            acc[1][1] = fmaf(a4.y, b4.y, acc[1][1]);
            acc[1][2] = fmaf(a4.y, b4.z, acc[1][2]);
            acc[1][3] = fmaf(a4.y, b4.w, acc[1][3]);
            acc[2][0] = fmaf(a4.z, b4.x, acc[2][0]);
            acc[2][1] = fmaf(a4.z, b4.y, acc[2][1]);
            acc[2][2] = fmaf(a4.z, b4.z, acc[2][2]);
            acc[2][3] = fmaf(a4.z, b4.w, acc[2][3]);
            acc[3][0] = fmaf(a4.w, b4.x, acc[3][0]);
            acc[3][1] = fmaf(a4.w, b4.y, acc[3][1]);
            acc[3][2] = fmaf(a4.w, b4.z, acc[3][2]);
            acc[3][3] = fmaf(a4.w, b4.w, acc[3][3]);
        }
        __syncthreads();
    }

    float* Cp = C + (size_t)(m0 + tm) * N + n0 + tn;
    if (gridDim.z == 1) {
        #pragma unroll
        for (int i = 0; i < 4; i++) {
            #pragma unroll
            for (int j = 0; j < 4; j++)
                Cp[i * N + j] = acc[i][j] + bias[n0 + tn + j];
        }
    } else {
        #pragma unroll
        for (int i = 0; i < 4; i++)
            #pragma unroll
            for (int j = 0; j < 4; j++)
                atomicAdd(&Cp[i * N + j], acc[i][j]);
    }
}

// ---------------------------------------------------------------------------
// scores: out[b, 0]   = -|| relu(p_lfs[b] - emb[b]) ||
//         out[b, 1+n] = -|| relu(n_lfs[n] - emb[b]) ||
// One block per b, emb row in smem, one warp per score, float4 loads.
// ---------------------------------------------------------------------------
__global__ __launch_bounds__(256) void scores_kernel(
    const float* __restrict__ p_lfs, const float* __restrict__ n_lfs,
    const float* __restrict__ emb, float* __restrict__ out)
{
    const int b = blockIdx.x;
    __shared__ float se[EMB_D];
    for (int d = threadIdx.x; d < EMB_D; d += blockDim.x)
        se[d] = emb[b * EMB_D + d];
    __syncthreads();

    const int warp = threadIdx.x >> 5;
    const int lane = threadIdx.x & 31;
    const int nwarp = blockDim.x >> 5;
    const float4* se4 = (const float4*)se;

    for (int s = warp; s <= NNEG; s += nwarp) {
        const float* lf = (s == 0) ? (p_lfs + b * EMB_D)
                                   : (n_lfs + (size_t)(s - 1) * EMB_D);
        const float4* lf4 = (const float4*)lf;
        float acc = 0.f;
        #pragma unroll
        for (int d = lane; d < EMB_D / 4; d += 32) {
            float4 l = lf4[d];
            float4 e = se4[d];
            float d0 = fmaxf(l.x - e.x, 0.f);
            float d1 = fmaxf(l.y - e.y, 0.f);
            float d2 = fmaxf(l.z - e.z, 0.f);
            float d3 = fmaxf(l.w - e.w, 0.f);
            acc = fmaf(d0, d0, acc);
            acc = fmaf(d1, d1, acc);
            acc = fmaf(d2, d2, acc);
            acc = fmaf(d3, d3, acc);
        }
        #pragma unroll
        for (int o = 16; o; o >>= 1)
            acc += __shfl_xor_sync(0xffffffffu, acc, o);
        if (lane == 0) out[b * (NNEG + 1) + s] = -sqrtf(acc);
    }
}

// ---------------------------------------------------------------------------
extern "C" void kernel_launch(void* const* d_in, const int* in_sizes, int n_in,
                              void* d_out, int out_size) {
    (void)in_sizes; (void)n_in; (void)out_size;
    const float* vfs      = (const float*)d_in[0];   // [256, 4096]
    const float* p_lfs    = (const float*)d_in[1];   // [256, 512]
    const float* n_lfs    = (const float*)d_in[2];   // [512, 512]
    const float* W_hidden = (const float*)d_in[3];   // [2048, 4096]
    const float* b_hidden = (const float*)d_in[4];   // [2048]
    const float* W_embed  = (const float*)d_in[5];   // [512, 2048]
    const float* b_embed  = (const float*)d_in[6];   // [512]
    float* out = (float*)d_out;                      // [256, 513]

    float* hid;
    float* emb;
    cudaGetSymbolAddress((void**)&hid, g_hidden);
    cudaGetSymbolAddress((void**)&emb, g_emb);

    // GEMM2 target pre-initialized with bias (split-K accumulates on top)
    init_emb_kernel<<<(BB * EMB_D + 255) / 256, 256>>>(b_embed);

    // GEMM1: hid = vfs @ W_hidden^T + b_hidden   (grid 32x8 = 256 blocks)
    {
        dim3 grid(HID_D / 64, BB / 32, 1);
        sgemm_nt<<<grid, 128>>>(vfs, W_hidden, b_hidden, hid, VF_D, HID_D, VF_D);
    }

    // GEMM2: emb += hid @ W_embed^T   (split-K=4, grid 8x8x4 = 256 blocks)
    {
        dim3 grid(EMB_D / 64, BB / 32, 4);
        sgemm_nt<<<grid, 128>>>(hid, W_embed, b_embed, emb, HID_D, EMB_D, HID_D / 4);
    }

    // scores
    scores_kernel<<<BB, 256>>>(p_lfs, n_lfs, emb, out);
}

// round 3
// speedup vs baseline: 1.9511x; 1.9511x over previous
#include <cuda_runtime.h>
#include <cuda_bf16.h>
#include <math.h>
#include <stdint.h>

#define VF_D  4096
#define HID_D 2048
#define EMB_D 512
#define BB    256
#define NNEG  512

// ---------------- static scratch (no runtime allocation allowed) -----------
__device__ float g_hidden[BB * HID_D];                     // fp32 GEMM1 out
__device__ float g_emb[BB * EMB_D];                        // fp32 GEMM2 out
__device__ __nv_bfloat16 g_Whi[HID_D * VF_D], g_Wlo[HID_D * VF_D];
__device__ __nv_bfloat16 g_Ehi[EMB_D * HID_D], g_Elo[EMB_D * HID_D];
__device__ __nv_bfloat16 g_Vhi[BB * VF_D],   g_Vlo[BB * VF_D];
__device__ __nv_bfloat16 g_Hhi[BB * HID_D],  g_Hlo[BB * HID_D];

// ---------------------------------------------------------------------------
// bias init: hidden[b][h] = b_hidden[h]; emb[b][e] = b_embed[e]
// (both GEMMs accumulate with atomicAdd on top)
// ---------------------------------------------------------------------------
__global__ void init_bias_kernel(const float* __restrict__ bh,
                                 const float* __restrict__ be) {
    int i = blockIdx.x * blockDim.x + threadIdx.x;
    if (i < BB * HID_D) g_hidden[i] = bh[i & (HID_D - 1)];
    if (i < BB * EMB_D) g_emb[i] = be[i & (EMB_D - 1)];
}

// ---------------------------------------------------------------------------
// fp32 -> (bf16 hi, bf16 lo) split, vectorized
// ---------------------------------------------------------------------------
__global__ void convert_split_kernel(const float4* __restrict__ in,
                                     uint2* __restrict__ hi,
                                     uint2* __restrict__ lo, int n4) {
    int i = blockIdx.x * blockDim.x + threadIdx.x;
    if (i >= n4) return;
    float4 f = in[i];
    __nv_bfloat16 hx = __float2bfloat16(f.x);
    __nv_bfloat16 hy = __float2bfloat16(f.y);
    __nv_bfloat16 hz = __float2bfloat16(f.z);
    __nv_bfloat16 hw = __float2bfloat16(f.w);
    __nv_bfloat16 lx = __float2bfloat16(f.x - __bfloat162float(hx));
    __nv_bfloat16 ly = __float2bfloat16(f.y - __bfloat162float(hy));
    __nv_bfloat16 lz = __float2bfloat16(f.z - __bfloat162float(hz));
    __nv_bfloat16 lw = __float2bfloat16(f.w - __bfloat162float(hw));
    __nv_bfloat162 h01 = __halves2bfloat162(hx, hy);
    __nv_bfloat162 h23 = __halves2bfloat162(hz, hw);
    __nv_bfloat162 l01 = __halves2bfloat162(lx, ly);
    __nv_bfloat162 l23 = __halves2bfloat162(lz, lw);
    uint2 hv, lv;
    hv.x = *reinterpret_cast<uint32_t*>(&h01);
    hv.y = *reinterpret_cast<uint32_t*>(&h23);
    lv.x = *reinterpret_cast<uint32_t*>(&l01);
    lv.y = *reinterpret_cast<uint32_t*>(&l23);
    hi[i] = hv;
    lo[i] = lv;
}

// ---------------------------------------------------------------------------
// mma.sync m16n8k16 bf16 helper
// ---------------------------------------------------------------------------
__device__ __forceinline__ void mma_bf16(float* c, const uint32_t* a,
                                         uint32_t b0, uint32_t b1) {
    asm volatile(
        "mma.sync.aligned.m16n8k16.row.col.f32.bf16.bf16.f32 "
        "{%0,%1,%2,%3}, {%4,%5,%6,%7}, {%8,%9}, {%0,%1,%2,%3};"
        : "+f"(c[0]), "+f"(c[1]), "+f"(c[2]), "+f"(c[3])
        : "r"(a[0]), "r"(a[1]), "r"(a[2]), "r"(a[3]), "r"(b0), "r"(b1));
}

__device__ __forceinline__ uint32_t lds2(const __nv_bfloat16* s, int idx) {
    return *reinterpret_cast<const uint32_t*>(s + idx);
}

// ---------------------------------------------------------------------------
// C[M,N] += A[M,K] @ B[N,K]^T  via bf16-split tensor core MMA.
// BM=128, BN=64, BK=32, 256 threads (8 warps: 4m x 2n, warp tile 32x32).
// Split-K via gridDim.z; always atomicAdd into bias-pre-initialized C.
// All dims divide tiles exactly for the fixed shapes.
// ---------------------------------------------------------------------------
#define ASTR 40   // padded bf16 row stride (conflict-free fragment LDS)

__global__ __launch_bounds__(256) void bgemm_nt(
    const __nv_bfloat16* __restrict__ Ahi, const __nv_bfloat16* __restrict__ Alo,
    const __nv_bfloat16* __restrict__ Bhi, const __nv_bfloat16* __restrict__ Blo,
    float* __restrict__ C, int lda, int N, int kchunk)
{
    __shared__ __nv_bfloat16 sAh[128 * ASTR];
    __shared__ __nv_bfloat16 sAl[128 * ASTR];
    __shared__ __nv_bfloat16 sBh[64 * ASTR];
    __shared__ __nv_bfloat16 sBl[64 * ASTR];

    const int tid = threadIdx.x, lane = tid & 31, wid = tid >> 5;
    const int wm = wid >> 1, wn = wid & 1;
    const int m0 = blockIdx.y * 128, n0 = blockIdx.x * 64;
    const int kbase = blockIdx.z * kchunk;

    // global-load assignment: 8 bf16 (uint4) per load, along K
    const int ar = tid >> 2;              // 0..63  (A second half at ar+64)
    const int ak = (tid & 3) * 8;         // 0,8,16,24

    const size_t aoff0 = (size_t)(m0 + ar) * lda + kbase + ak;
    const size_t aoff1 = aoff0 + (size_t)64 * lda;
    const size_t boff  = (size_t)(n0 + ar) * lda + kbase + ak;

    const int g = lane >> 2, tg = lane & 3;

    float acc[2][4][4];
    #pragma unroll
    for (int i = 0; i < 2; i++)
        #pragma unroll
        for (int j = 0; j < 4; j++)
            #pragma unroll
            for (int q = 0; q < 4; q++) acc[i][j][q] = 0.f;

    // prefetch tile 0
    uint4 rAh0 = *(const uint4*)(Ahi + aoff0);
    uint4 rAh1 = *(const uint4*)(Ahi + aoff1);
    uint4 rAl0 = *(const uint4*)(Alo + aoff0);
    uint4 rAl1 = *(const uint4*)(Alo + aoff1);
    uint4 rBh  = *(const uint4*)(Bhi + boff);
    uint4 rBl  = *(const uint4*)(Blo + boff);

    const int nk = kchunk / 32;
    for (int kt = 0; kt < nk; kt++) {
        *(uint4*)&sAh[ar * ASTR + ak]        = rAh0;
        *(uint4*)&sAh[(ar + 64) * ASTR + ak] = rAh1;
        *(uint4*)&sAl[ar * ASTR + ak]        = rAl0;
        *(uint4*)&sAl[(ar + 64) * ASTR + ak] = rAl1;
        *(uint4*)&sBh[ar * ASTR + ak]        = rBh;
        *(uint4*)&sBl[ar * ASTR + ak]        = rBl;
        __syncthreads();

        if (kt + 1 < nk) {
            int ko = (kt + 1) * 32;
            rAh0 = *(const uint4*)(Ahi + aoff0 + ko);
            rAh1 = *(const uint4*)(Ahi + aoff1 + ko);
            rAl0 = *(const uint4*)(Alo + aoff0 + ko);
            rAl1 = *(const uint4*)(Alo + aoff1 + ko);
            rBh  = *(const uint4*)(Bhi + boff + ko);
            rBl  = *(const uint4*)(Blo + boff + ko);
        }

        #pragma unroll
        for (int kk = 0; kk < 32; kk += 16) {
            uint32_t Ah[2][4], Al[2][4];
            #pragma unroll
            for (int im = 0; im < 2; im++) {
                int r = (wm * 32 + im * 16 + g) * ASTR + kk + tg * 2;
                Ah[im][0] = lds2(sAh, r);
                Ah[im][1] = lds2(sAh, r + 8 * ASTR);
                Ah[im][2] = lds2(sAh, r + 8);
                Ah[im][3] = lds2(sAh, r + 8 * ASTR + 8);
                Al[im][0] = lds2(sAl, r);
                Al[im][1] = lds2(sAl, r + 8 * ASTR);
                Al[im][2] = lds2(sAl, r + 8);
                Al[im][3] = lds2(sAl, r + 8 * ASTR + 8);
            }
            #pragma unroll
            for (int in = 0; in < 4; in++) {
                int r = (wn * 32 + in * 8 + g) * ASTR + kk + tg * 2;
                uint32_t Bh0 = lds2(sBh, r), Bh1 = lds2(sBh, r + 8);
                uint32_t Bl0 = lds2(sBl, r), Bl1 = lds2(sBl, r + 8);
                #pragma unroll
                for (int im = 0; im < 2; im++) {
                    mma_bf16(acc[im][in], Ah[im], Bh0, Bh1);
                    mma_bf16(acc[im][in], Ah[im], Bl0, Bl1);
                    mma_bf16(acc[im][in], Al[im], Bh0, Bh1);
                }
            }
        }
        __syncthreads();
    }

    // epilogue: atomic accumulate (split-K safe; C pre-initialized with bias)
    #pragma unroll
    for (int im = 0; im < 2; im++) {
        int mr = m0 + wm * 32 + im * 16 + g;
        #pragma unroll
        for (int in = 0; in < 4; in++) {
            int nc = n0 + wn * 32 + in * 8 + tg * 2;
            atomicAdd(&C[(size_t)mr * N + nc],           acc[im][in][0]);
            atomicAdd(&C[(size_t)mr * N + nc + 1],       acc[im][in][1]);
            atomicAdd(&C[(size_t)(mr + 8) * N + nc],     acc[im][in][2]);
            atomicAdd(&C[(size_t)(mr + 8) * N + nc + 1], acc[im][in][3]);
        }
    }
}

// ---------------------------------------------------------------------------
// negative scores, tiled like a GEMM: out[b][1+s] = -||relu(n_lfs[s]-emb[b])||
// Block tile: 32 s x 32 b, d-chunks of 32 in smem (transposed), 2x2 micro.
// Grid: (NNEG/32=16, BB/32=8) = 128 blocks.
// ---------------------------------------------------------------------------
__global__ __launch_bounds__(256) void neg_scores_kernel(
    const float* __restrict__ n_lfs, float* __restrict__ out)
{
    __shared__ float Ssm[32][34];   // [d][s]
    __shared__ float Esm[32][34];   // [d][b]

    const int tid = threadIdx.x;
    const int s0 = blockIdx.x * 32, b0 = blockIdx.y * 32;
    const int ts = (tid >> 4) * 2, tb = (tid & 15) * 2;
    const int r = tid >> 3, cq = (tid & 7);   // load: row r, float4 col cq

    const float4* nl4 = (const float4*)n_lfs;
    const float4* em4 = (const float4*)g_emb;

    float acc[2][2] = {};

    float4 sv = nl4[(size_t)(s0 + r) * (EMB_D / 4) + cq];
    float4 ev = em4[(size_t)(b0 + r) * (EMB_D / 4) + cq];

    for (int dc = 0; dc < EMB_D; dc += 32) {
        __syncthreads();
        int c = cq * 4;
        Ssm[c + 0][r] = sv.x; Ssm[c + 1][r] = sv.y;
        Ssm[c + 2][r] = sv.z; Ssm[c + 3][r] = sv.w;
        Esm[c + 0][r] = ev.x; Esm[c + 1][r] = ev.y;
        Esm[c + 2][r] = ev.z; Esm[c + 3][r] = ev.w;
        __syncthreads();

        if (dc + 32 < EMB_D) {
            sv = nl4[(size_t)(s0 + r) * (EMB_D / 4) + ((dc + 32) >> 2) + cq];
            ev = em4[(size_t)(b0 + r) * (EMB_D / 4) + ((dc + 32) >> 2) + cq];
        }

        #pragma unroll
        for (int d = 0; d < 32; d++) {
            float2 s2 = *(const float2*)&Ssm[d][ts];
            float2 e2 = *(const float2*)&Esm[d][tb];
            float d00 = fmaxf(s2.x - e2.x, 0.f);
            float d01 = fmaxf(s2.x - e2.y, 0.f);
            float d10 = fmaxf(s2.y - e2.x, 0.f);
            float d11 = fmaxf(s2.y - e2.y, 0.f);
            acc[0][0] = fmaf(d00, d00, acc[0][0]);
            acc[0][1] = fmaf(d01, d01, acc[0][1]);
            acc[1][0] = fmaf(d10, d10, acc[1][0]);
            acc[1][1] = fmaf(d11, d11, acc[1][1]);
        }
    }

    #pragma unroll
    for (int i = 0; i < 2; i++)
        #pragma unroll
        for (int j = 0; j < 2; j++)
            out[(size_t)(b0 + tb + j) * (NNEG + 1) + 1 + s0 + ts + i] =
                -sqrtf(acc[i][j]);
}

// ---------------------------------------------------------------------------
// positive scores: out[b][0] = -||relu(p_lfs[b] - emb[b])||, warp per b
// ---------------------------------------------------------------------------
__global__ __launch_bounds__(256) void pos_scores_kernel(
    const float* __restrict__ p_lfs, float* __restrict__ out)
{
    const int wid = threadIdx.x >> 5, lane = threadIdx.x & 31;
    const int b = blockIdx.x * 8 + wid;
    const float4* lf4 = (const float4*)(p_lfs + (size_t)b * EMB_D);
    const float4* em4 = (const float4*)(g_emb + (size_t)b * EMB_D);
    float acc = 0.f;
    #pragma unroll
    for (int d = lane; d < EMB_D / 4; d += 32) {
        float4 l = lf4[d], e = em4[d];
        float d0 = fmaxf(l.x - e.x, 0.f);
        float d1 = fmaxf(l.y - e.y, 0.f);
        float d2 = fmaxf(l.z - e.z, 0.f);
        float d3 = fmaxf(l.w - e.w, 0.f);
        acc = fmaf(d0, d0, acc);
        acc = fmaf(d1, d1, acc);
        acc = fmaf(d2, d2, acc);
        acc = fmaf(d3, d3, acc);
    }
    #pragma unroll
    for (int o = 16; o; o >>= 1) acc += __shfl_xor_sync(0xffffffffu, acc, o);
    if (lane == 0) out[(size_t)b * (NNEG + 1)] = -sqrtf(acc);
}

// ---------------------------------------------------------------------------
extern "C" void kernel_launch(void* const* d_in, const int* in_sizes, int n_in,
                              void* d_out, int out_size) {
    (void)in_sizes; (void)n_in; (void)out_size;
    const float* vfs      = (const float*)d_in[0];   // [256, 4096]
    const float* p_lfs    = (const float*)d_in[1];   // [256, 512]
    const float* n_lfs    = (const float*)d_in[2];   // [512, 512]
    const float* W_hidden = (const float*)d_in[3];   // [2048, 4096]
    const float* b_hidden = (const float*)d_in[4];   // [2048]
    const float* W_embed  = (const float*)d_in[5];   // [512, 2048]
    const float* b_embed  = (const float*)d_in[6];   // [512]
    float* out = (float*)d_out;                      // [256, 513]

    float *hid, *emb;
    __nv_bfloat16 *Whi, *Wlo, *Ehi, *Elo, *Vhi, *Vlo, *Hhi, *Hlo;
    cudaGetSymbolAddress((void**)&hid, g_hidden);
    cudaGetSymbolAddress((void**)&emb, g_emb);
    cudaGetSymbolAddress((void**)&Whi, g_Whi);
    cudaGetSymbolAddress((void**)&Wlo, g_Wlo);
    cudaGetSymbolAddress((void**)&Ehi, g_Ehi);
    cudaGetSymbolAddress((void**)&Elo, g_Elo);
    cudaGetSymbolAddress((void**)&Vhi, g_Vhi);
    cudaGetSymbolAddress((void**)&Vlo, g_Vlo);
    cudaGetSymbolAddress((void**)&Hhi, g_Hhi);
    cudaGetSymbolAddress((void**)&Hlo, g_Hlo);

    // 1. bias pre-init of both GEMM outputs
    init_bias_kernel<<<(BB * HID_D + 255) / 256, 256>>>(b_hidden, b_embed);

    // 2. split-convert weights + activations to bf16 hi/lo
    {
        int n4 = HID_D * VF_D / 4;
        convert_split_kernel<<<(n4 + 255) / 256, 256>>>(
            (const float4*)W_hidden, (uint2*)Whi, (uint2*)Wlo, n4);
        n4 = BB * VF_D / 4;
        convert_split_kernel<<<(n4 + 255) / 256, 256>>>(
            (const float4*)vfs, (uint2*)Vhi, (uint2*)Vlo, n4);
        n4 = EMB_D * HID_D / 4;
        convert_split_kernel<<<(n4 + 255) / 256, 256>>>(
            (const float4*)W_embed, (uint2*)Ehi, (uint2*)Elo, n4);
    }

    // 3. GEMM1: hidden += vfs @ W_hidden^T   (grid 32x2x2 = 128 blocks)
    {
        dim3 grid(HID_D / 64, BB / 128, 2);
        bgemm_nt<<<grid, 256>>>(Vhi, Vlo, Whi, Wlo, hid, VF_D, HID_D, VF_D / 2);
    }

    // 4. split-convert hidden
    {
        int n4 = BB * HID_D / 4;
        convert_split_kernel<<<(n4 + 255) / 256, 256>>>(
            (const float4*)hid, (uint2*)Hhi, (uint2*)Hlo, n4);
    }

    // 5. GEMM2: emb += hidden @ W_embed^T   (grid 8x2x8 = 128 blocks)
    {
        dim3 grid(EMB_D / 64, BB / 128, 8);
        bgemm_nt<<<grid, 256>>>(Hhi, Hlo, Ehi, Elo, emb, HID_D, EMB_D, HID_D / 8);
    }

    // 6. scores
    pos_scores_kernel<<<BB / 8, 256>>>(p_lfs, out);
    {
        dim3 grid(NNEG / 32, BB / 32);
        neg_scores_kernel<<<grid, 256>>>(n_lfs, out);
    }
}

// round 6
// speedup vs baseline: 2.3522x; 1.2056x over previous
#include <cuda_runtime.h>
#include <cuda_bf16.h>
#include <math.h>
#include <stdint.h>

#define VF_D  4096
#define HID_D 2048
#define EMB_D 512
#define BB    256
#define NNEG  512

// ---------------- static scratch ------------------------------------------
__device__ float g_emb[BB * EMB_D];
__device__ float g_hpart[4 * BB * HID_D];     // GEMM1 split-K partials
__device__ float g_epart[8 * BB * EMB_D];     // GEMM2 split-K partials
__device__ __nv_bfloat16 g_Whi[HID_D * VF_D], g_Wlo[HID_D * VF_D];
__device__ __nv_bfloat16 g_Ehi[EMB_D * HID_D], g_Elo[EMB_D * HID_D];
__device__ __nv_bfloat16 g_Vhi[BB * VF_D],   g_Vlo[BB * VF_D];
__device__ __nv_bfloat16 g_Hhi[BB * HID_D],  g_Hlo[BB * HID_D];

// ---------------- asm helpers ---------------------------------------------
__device__ __forceinline__ uint32_t smem_u32(const void* p) {
    uint32_t a;
    asm("{ .reg .u64 t; cvta.to.shared.u64 t, %1; cvt.u32.u64 %0, t; }"
        : "=r"(a) : "l"(p));
    return a;
}
#define CP_ASYNC(dst, src) \
    asm volatile("cp.async.cg.shared.global [%0], [%1], 16;" \
                 :: "r"(dst), "l"(src) : "memory")
#define CP_COMMIT() asm volatile("cp.async.commit_group;" ::: "memory")
#define CP_WAIT2()  asm volatile("cp.async.wait_group 2;" ::: "memory")

__device__ __forceinline__ void ldm4(uint32_t* r, uint32_t addr) {
    asm volatile("ldmatrix.sync.aligned.m8n8.x4.shared.b16 {%0,%1,%2,%3}, [%4];"
                 : "=r"(r[0]), "=r"(r[1]), "=r"(r[2]), "=r"(r[3]) : "r"(addr));
}
__device__ __forceinline__ void mma_bf16(float* c, const uint32_t* a,
                                         uint32_t b0, uint32_t b1) {
    asm volatile(
        "mma.sync.aligned.m16n8k16.row.col.f32.bf16.bf16.f32 "
        "{%0,%1,%2,%3}, {%4,%5,%6,%7}, {%8,%9}, {%0,%1,%2,%3};"
        : "+f"(c[0]), "+f"(c[1]), "+f"(c[2]), "+f"(c[3])
        : "r"(a[0]), "r"(a[1]), "r"(a[2]), "r"(a[3]), "r"(b0), "r"(b1));
}

// ---------------------------------------------------------------------------
// bf16-split NT GEMM via mma.sync + cp.async 4-stage pipeline.
// C_part[z][M=256][ldc] = A[M,K] @ B[N,K]^T   (3-term hi/lo split, fp32 acc)
// BM=128, BN template (128 or 64), BK=32, 256 threads = 8 warps (2m x 4n).
// smem per stage: Ah(128x80B) Al Bh(BNx80B) Bl ; 80B rows -> conflict-free
// ldmatrix. Per-split plain stores into its own partial buffer (no atomics).
// ---------------------------------------------------------------------------
template <int BN>
__global__ __launch_bounds__(256, 1) void mma_gemm(
    const __nv_bfloat16* __restrict__ Ahi, const __nv_bfloat16* __restrict__ Alo,
    const __nv_bfloat16* __restrict__ Bhi, const __nv_bfloat16* __restrict__ Blo,
    float* __restrict__ Cpart, int lda, int ldc, int kchunk)
{
    constexpr int STAGE = 20480 + BN * 160;   // Ah 10240 | Al 10240 | Bh | Bl
    constexpr int OFF_AL = 10240;
    constexpr int OFF_B  = 20480;
    constexpr int OFF_BL = 20480 + BN * 80;
    constexpr int ITER_B = BN / 32;           // B cp.async chunks per thread
    constexpr int NW = BN / 64;               // n16 ldmatrix groups per warp
    constexpr int NT = BN / 32;               // n8 mma tiles per warp

    extern __shared__ char smem[];
    const uint32_t sb = smem_u32(smem);
    const int tid = threadIdx.x, lane = tid & 31, wid = tid >> 5;
    const int wm = wid >> 2, wn = wid & 3;
    const int m0 = blockIdx.y * 128, n0 = blockIdx.x * BN;
    const int kbase = blockIdx.z * kchunk;
    const int nk = kchunk / 32;

    // ---- cp.async loader assignments (16B chunks) ----
    const __nv_bfloat16* asrc[4]; int adst[4];
    #pragma unroll
    for (int i = 0; i < 4; i++) {
        int c = tid + i * 256;                 // 0..1023
        int plane = c >> 9, row = (c >> 2) & 127, col = c & 3;
        asrc[i] = (plane ? Alo : Ahi) + (size_t)(m0 + row) * lda + kbase + col * 8;
        adst[i] = plane * OFF_AL + row * 80 + col * 16;
    }
    const __nv_bfloat16* bsrc[ITER_B]; int bdst[ITER_B];
    #pragma unroll
    for (int i = 0; i < ITER_B; i++) {
        int c = tid + i * 256;                 // 0..BN*8-1
        int plane = c / (BN * 4), row = (c >> 2) & (BN - 1), col = c & 3;
        bsrc[i] = (plane ? Blo : Bhi) + (size_t)(n0 + row) * lda + kbase + col * 8;
        bdst[i] = OFF_B + plane * (BN * 80) + row * 80 + col * 16;
    }

    // ---- ldmatrix addresses (within-stage offsets) ----
    int aAd[4];
    #pragma unroll
    for (int i = 0; i < 4; i++)
        aAd[i] = (wm * 64 + i * 16 + (lane & 15)) * 80 + (lane >> 4) * 16;
    int bAd[NW];
    #pragma unroll
    for (int j = 0; j < NW; j++)
        bAd[j] = OFF_B + (wn * (BN / 4) + j * 16 + (lane & 7) +
                          ((lane >> 4) & 1) * 8) * 80 + ((lane >> 3) & 1) * 16;

    float acc[4][NT][4];
    #pragma unroll
    for (int i = 0; i < 4; i++)
        #pragma unroll
        for (int j = 0; j < NT; j++)
            #pragma unroll
            for (int q = 0; q < 4; q++) acc[i][j][q] = 0.f;

    // ---- prologue: issue stages 0..2 ----
    #pragma unroll
    for (int p = 0; p < 3; p++) {
        uint32_t base = sb + p * STAGE;
        int ko = p * 32;
        #pragma unroll
        for (int i = 0; i < 4; i++) CP_ASYNC(base + adst[i], asrc[i] + ko);
        #pragma unroll
        for (int i = 0; i < ITER_B; i++) CP_ASYNC(base + bdst[i], bsrc[i] + ko);
        CP_COMMIT();
    }

    // ---- main loop ----
    for (int kt = 0; kt < nk; kt++) {
        CP_WAIT2();
        __syncthreads();

        if (kt + 3 < nk) {   // issue stage kt+3 into buffer (kt+3)&3 == (kt-1)&3
            uint32_t base = sb + ((kt + 3) & 3) * STAGE;
            int ko = (kt + 3) * 32;
            #pragma unroll
            for (int i = 0; i < 4; i++) CP_ASYNC(base + adst[i], asrc[i] + ko);
            #pragma unroll
            for (int i = 0; i < ITER_B; i++) CP_ASYNC(base + bdst[i], bsrc[i] + ko);
        }
        CP_COMMIT();         // always one group/iter (empty near tail)

        const uint32_t st = sb + (kt & 3) * STAGE;
        #pragma unroll
        for (int kk = 0; kk < 64; kk += 32) {   // two k16 halves (bytes)
            uint32_t Ah[4][4], Al[4][4], Bh[NW][4], Bl[NW][4];
            #pragma unroll
            for (int i = 0; i < 4; i++) {
                ldm4(Ah[i], st + aAd[i] + kk);
                ldm4(Al[i], st + OFF_AL + aAd[i] + kk);
            }
            #pragma unroll
            for (int j = 0; j < NW; j++) {
                ldm4(Bh[j], st + bAd[j] + kk);
                ldm4(Bl[j], st + (OFF_BL - OFF_B) + bAd[j] + kk);
            }
            #pragma unroll
            for (int i = 0; i < 4; i++)
                #pragma unroll
                for (int jn = 0; jn < NT; jn++) {
                    const int j = jn >> 1, h = (jn & 1) * 2;
                    mma_bf16(acc[i][jn], Ah[i], Bh[j][h], Bh[j][h + 1]);
                    mma_bf16(acc[i][jn], Ah[i], Bl[j][h], Bl[j][h + 1]);
                    mma_bf16(acc[i][jn], Al[i], Bh[j][h], Bh[j][h + 1]);
                }
        }
    }

    // ---- epilogue: plain stores into this split's partial buffer ----
    float* Cp = Cpart + (size_t)blockIdx.z * BB * ldc;
    #pragma unroll
    for (int i = 0; i < 4; i++) {
        const int m = m0 + wm * 64 + i * 16 + (lane >> 2);
        #pragma unroll
        for (int jn = 0; jn < NT; jn++) {
            const int n = n0 + wn * (BN / 4) + jn * 8 + (lane & 3) * 2;
            *(float2*)&Cp[(size_t)m * ldc + n] =
                make_float2(acc[i][jn][0], acc[i][jn][1]);
            *(float2*)&Cp[(size_t)(m + 8) * ldc + n] =
                make_float2(acc[i][jn][2], acc[i][jn][3]);
        }
    }
}

// ---------------------------------------------------------------------------
// fp32 -> bf16 hi/lo split, 4 independent float4 per thread
// ---------------------------------------------------------------------------
__device__ __forceinline__ void split4(float4 f, uint2& hv, uint2& lv) {
    __nv_bfloat16 hx = __float2bfloat16_rn(f.x);
    __nv_bfloat16 hy = __float2bfloat16_rn(f.y);
    __nv_bfloat16 hz = __float2bfloat16_rn(f.z);
    __nv_bfloat16 hw = __float2bfloat16_rn(f.w);
    __nv_bfloat16 lx = __float2bfloat16_rn(f.x - __bfloat162float(hx));
    __nv_bfloat16 ly = __float2bfloat16_rn(f.y - __bfloat162float(hy));
    __nv_bfloat16 lz = __float2bfloat16_rn(f.z - __bfloat162float(hz));
    __nv_bfloat16 lw = __float2bfloat16_rn(f.w - __bfloat162float(hw));
    hv.x = ((uint32_t)__bfloat16_as_ushort(hy) << 16) | __bfloat16_as_ushort(hx);
    hv.y = ((uint32_t)__bfloat16_as_ushort(hw) << 16) | __bfloat16_as_ushort(hz);
    lv.x = ((uint32_t)__bfloat16_as_ushort(ly) << 16) | __bfloat16_as_ushort(lx);
    lv.y = ((uint32_t)__bfloat16_as_ushort(lw) << 16) | __bfloat16_as_ushort(lz);
}

__global__ __launch_bounds__(256) void convert_split4(
    const float4* __restrict__ in, uint2* __restrict__ hi,
    uint2* __restrict__ lo)
{
    int base = blockIdx.x * 1024 + threadIdx.x;
    float4 f[4];
    #pragma unroll
    for (int i = 0; i < 4; i++) f[i] = in[base + i * 256];
    #pragma unroll
    for (int i = 0; i < 4; i++) {
        uint2 hv, lv;
        split4(f[i], hv, lv);
        hi[base + i * 256] = hv;
        lo[base + i * 256] = lv;
    }
}

// ---------------------------------------------------------------------------
// hidden = sum(4 partials) + bias  -> bf16 hi/lo planes  (float4 grain)
// ---------------------------------------------------------------------------
__global__ __launch_bounds__(256) void reduce_hidden(
    const float* __restrict__ bias)
{
    int i = blockIdx.x * 256 + threadIdx.x;           // 0..131071 float4s
    const float4* p = (const float4*)g_hpart;
    float4 v = p[i];
    #pragma unroll
    for (int s = 1; s < 4; s++) {
        float4 t = p[i + s * (BB * HID_D / 4)];
        v.x += t.x; v.y += t.y; v.z += t.z; v.w += t.w;
    }
    int e = (i * 4) & (HID_D - 1);
    float4 b = *(const float4*)(bias + e);
    v.x += b.x; v.y += b.y; v.z += b.z; v.w += b.w;
    uint2 hv, lv;
    split4(v, hv, lv);
    ((uint2*)g_Hhi)[i] = hv;
    ((uint2*)g_Hlo)[i] = lv;
}

// ---------------------------------------------------------------------------
// emb = sum(8 partials) + bias   (float4 grain)
// ---------------------------------------------------------------------------
__global__ __launch_bounds__(256) void reduce_emb(const float* __restrict__ bias)
{
    int i = blockIdx.x * 256 + threadIdx.x;           // 0..32767 float4s
    const float4* p = (const float4*)g_epart;
    float4 v = p[i];
    #pragma unroll
    for (int s = 1; s < 8; s++) {
        float4 t = p[i + s * (BB * EMB_D / 4)];
        v.x += t.x; v.y += t.y; v.z += t.z; v.w += t.w;
    }
    int e = (i * 4) & (EMB_D - 1);
    float4 b = *(const float4*)(bias + e);
    v.x += b.x; v.y += b.y; v.z += b.z; v.w += b.w;
    ((float4*)g_emb)[i] = v;
}

// ---------------------------------------------------------------------------
// negative scores (tiled): out[b][1+s] = -||relu(n_lfs[s]-emb[b])||
// ---------------------------------------------------------------------------
__global__ __launch_bounds__(256) void neg_scores_kernel(
    const float* __restrict__ n_lfs, float* __restrict__ out)
{
    __shared__ float Ssm[32][34];
    __shared__ float Esm[32][34];

    const int tid = threadIdx.x;
    const int s0 = blockIdx.x * 32, b0 = blockIdx.y * 32;
    const int ts = (tid >> 4) * 2, tb = (tid & 15) * 2;
    const int r = tid >> 3, cq = (tid & 7);

    const float4* nl4 = (const float4*)n_lfs;
    const float4* em4 = (const float4*)g_emb;

    float acc[2][2] = {};
    float4 sv = nl4[(size_t)(s0 + r) * (EMB_D / 4) + cq];
    float4 ev = em4[(size_t)(b0 + r) * (EMB_D / 4) + cq];

    for (int dc = 0; dc < EMB_D; dc += 32) {
        __syncthreads();
        int c = cq * 4;
        Ssm[c + 0][r] = sv.x; Ssm[c + 1][r] = sv.y;
        Ssm[c + 2][r] = sv.z; Ssm[c + 3][r] = sv.w;
        Esm[c + 0][r] = ev.x; Esm[c + 1][r] = ev.y;
        Esm[c + 2][r] = ev.z; Esm[c + 3][r] = ev.w;
        __syncthreads();

        if (dc + 32 < EMB_D) {
            sv = nl4[(size_t)(s0 + r) * (EMB_D / 4) + ((dc + 32) >> 2) + cq];
            ev = em4[(size_t)(b0 + r) * (EMB_D / 4) + ((dc + 32) >> 2) + cq];
        }
        #pragma unroll
        for (int d = 0; d < 32; d++) {
            float2 s2 = *(const float2*)&Ssm[d][ts];
            float2 e2 = *(const float2*)&Esm[d][tb];
            float d00 = fmaxf(s2.x - e2.x, 0.f);
            float d01 = fmaxf(s2.x - e2.y, 0.f);
            float d10 = fmaxf(s2.y - e2.x, 0.f);
            float d11 = fmaxf(s2.y - e2.y, 0.f);
            acc[0][0] = fmaf(d00, d00, acc[0][0]);
            acc[0][1] = fmaf(d01, d01, acc[0][1]);
            acc[1][0] = fmaf(d10, d10, acc[1][0]);
            acc[1][1] = fmaf(d11, d11, acc[1][1]);
        }
    }
    #pragma unroll
    for (int i = 0; i < 2; i++)
        #pragma unroll
        for (int j = 0; j < 2; j++)
            out[(size_t)(b0 + tb + j) * (NNEG + 1) + 1 + s0 + ts + i] =
                -sqrtf(acc[i][j]);
}

// ---------------------------------------------------------------------------
__global__ __launch_bounds__(256) void pos_scores_kernel(
    const float* __restrict__ p_lfs, float* __restrict__ out)
{
    const int wid = threadIdx.x >> 5, lane = threadIdx.x & 31;
    const int b = blockIdx.x * 8 + wid;
    const float4* lf4 = (const float4*)(p_lfs + (size_t)b * EMB_D);
    const float4* em4 = (const float4*)(g_emb + (size_t)b * EMB_D);
    float acc = 0.f;
    #pragma unroll
    for (int d = lane; d < EMB_D / 4; d += 32) {
        float4 l = lf4[d], e = em4[d];
        float d0 = fmaxf(l.x - e.x, 0.f);
        float d1 = fmaxf(l.y - e.y, 0.f);
        float d2 = fmaxf(l.z - e.z, 0.f);
        float d3 = fmaxf(l.w - e.w, 0.f);
        acc = fmaf(d0, d0, acc);
        acc = fmaf(d1, d1, acc);
        acc = fmaf(d2, d2, acc);
        acc = fmaf(d3, d3, acc);
    }
    #pragma unroll
    for (int o = 16; o; o >>= 1) acc += __shfl_xor_sync(0xffffffffu, acc, o);
    if (lane == 0) out[(size_t)b * (NNEG + 1)] = -sqrtf(acc);
}

// ---------------------------------------------------------------------------
extern "C" void kernel_launch(void* const* d_in, const int* in_sizes, int n_in,
                              void* d_out, int out_size) {
    (void)in_sizes; (void)n_in; (void)out_size;
    const float* vfs      = (const float*)d_in[0];
    const float* p_lfs    = (const float*)d_in[1];
    const float* n_lfs    = (const float*)d_in[2];
    const float* W_hidden = (const float*)d_in[3];
    const float* b_hidden = (const float*)d_in[4];
    const float* W_embed  = (const float*)d_in[5];
    const float* b_embed  = (const float*)d_in[6];
    float* out = (float*)d_out;

    float *hpart, *epart;
    __nv_bfloat16 *Whi, *Wlo, *Ehi, *Elo, *Vhi, *Vlo, *Hhi, *Hlo;
    cudaGetSymbolAddress((void**)&hpart, g_hpart);
    cudaGetSymbolAddress((void**)&epart, g_epart);
    cudaGetSymbolAddress((void**)&Whi, g_Whi);
    cudaGetSymbolAddress((void**)&Wlo, g_Wlo);
    cudaGetSymbolAddress((void**)&Ehi, g_Ehi);
    cudaGetSymbolAddress((void**)&Elo, g_Elo);
    cudaGetSymbolAddress((void**)&Vhi, g_Vhi);
    cudaGetSymbolAddress((void**)&Vlo, g_Vlo);
    cudaGetSymbolAddress((void**)&Hhi, g_Hhi);
    cudaGetSymbolAddress((void**)&Hlo, g_Hlo);

    cudaFuncSetAttribute(mma_gemm<128>,
                         cudaFuncAttributeMaxDynamicSharedMemorySize, 163840);
    cudaFuncSetAttribute(mma_gemm<64>,
                         cudaFuncAttributeMaxDynamicSharedMemorySize, 122880);

    // 1. split-convert weights + vfs
    convert_split4<<<HID_D * VF_D / 4096, 256>>>(
        (const float4*)W_hidden, (uint2*)Whi, (uint2*)Wlo);
    convert_split4<<<BB * VF_D / 4096, 256>>>(
        (const float4*)vfs, (uint2*)Vhi, (uint2*)Vlo);
    convert_split4<<<EMB_D * HID_D / 4096, 256>>>(
        (const float4*)W_embed, (uint2*)Ehi, (uint2*)Elo);

    // 2. GEMM1: hpart[z] = vfs @ W_hidden^T  (BM128/BN128, split-K=4, 128 CTAs)
    {
        dim3 grid(HID_D / 128, BB / 128, 4);
        mma_gemm<128><<<grid, 256, 163840>>>(Vhi, Vlo, Whi, Wlo, hpart,
                                             VF_D, HID_D, VF_D / 4);
    }

    // 3. hidden = sum + bias -> bf16 planes
    reduce_hidden<<<BB * HID_D / 1024, 256>>>(b_hidden);

    // 4. GEMM2: epart[z] = hidden @ W_embed^T (BM128/BN64, split-K=8, 128 CTAs)
    {
        dim3 grid(EMB_D / 64, BB / 128, 8);
        mma_gemm<64><<<grid, 256, 122880>>>(Hhi, Hlo, Ehi, Elo, epart,
                                            HID_D, EMB_D, HID_D / 8);
    }

    // 5. emb = sum + bias
    reduce_emb<<<BB * EMB_D / 1024, 256>>>(b_embed);

    // 6. scores
    pos_scores_kernel<<<BB / 8, 256>>>(p_lfs, out);
    {
        dim3 grid(NNEG / 32, BB / 32);
        neg_scores_kernel<<<grid, 256>>>(n_lfs, out);
    }
}